// round 1
// baseline (speedup 1.0000x reference)
#include <cuda_runtime.h>
#include <cstdint>

#define N_NODES 100000
#define EMB_DIM 128

// Scratch (allocations are forbidden; __device__ globals are the sanctioned path)
__device__ int   g_deg[N_NODES];
__device__ float g_dinv[N_NODES];

// ---------------------------------------------------------------------------
// 1) zero degree counters
__global__ void k_zero_deg() {
    int i = blockIdx.x * blockDim.x + threadIdx.x;
    if (i < N_NODES) g_deg[i] = 0;
}

// 2) histogram of source nodes (row). Self-loop contributes +1 later.
__global__ void k_count(const int* __restrict__ row, int E) {
    int i = blockIdx.x * blockDim.x + threadIdx.x;
    if (i < E) atomicAdd(&g_deg[row[i]], 1);
}

// 3) dinv = rsqrt(deg + 1)   (deg >= 1 always due to self loop, no zero case)
__global__ void k_dinv() {
    int i = blockIdx.x * blockDim.x + threadIdx.x;
    if (i < N_NODES) g_dinv[i] = rsqrtf((float)(g_deg[i] + 1));
}

// 4) self-loop pass: out[i] = dinv[i]^2 * emb[i]. One warp per node,
//    each lane handles one float4 (32 lanes * 16B = 512B = 128 floats).
__global__ void k_self(const float* __restrict__ emb, float* __restrict__ out) {
    int gtid = blockIdx.x * blockDim.x + threadIdx.x;
    int node = gtid >> 5;
    int lane = gtid & 31;
    if (node >= N_NODES) return;
    float w = g_dinv[node];
    w *= w;
    const float4* src = reinterpret_cast<const float4*>(emb) + (size_t)node * 32 + lane;
    float4 v = *src;
    v.x *= w; v.y *= w; v.z *= w; v.w *= w;
    float4* dst = reinterpret_cast<float4*>(out) + (size_t)node * 32 + lane;
    *dst = v;
}

// 5) edge scatter: one warp per edge. lane loads float4 of emb[row],
//    scales, and does a vector reduction (red.global.add.v4.f32) into out[col].
__global__ void __launch_bounds__(256) k_edge(const int* __restrict__ row,
                                              const int* __restrict__ col,
                                              const float* __restrict__ emb,
                                              float* __restrict__ out, int E) {
    int gtid = blockIdx.x * blockDim.x + threadIdx.x;
    int e    = gtid >> 5;
    int lane = gtid & 31;
    if (e >= E) return;
    int r = __ldg(&row[e]);   // all 32 lanes same address -> L1 broadcast
    int c = __ldg(&col[e]);
    float w = g_dinv[r] * g_dinv[c];
    const float4* src = reinterpret_cast<const float4*>(emb) + (size_t)r * 32 + lane;
    float4 v = *src;
    float* dst = out + (size_t)c * EMB_DIM + lane * 4;  // 16B aligned
    asm volatile("red.global.add.v4.f32 [%0], {%1, %2, %3, %4};"
                 :: "l"(dst), "f"(v.x * w), "f"(v.y * w), "f"(v.z * w), "f"(v.w * w)
                 : "memory");
}

// ---------------------------------------------------------------------------
extern "C" void kernel_launch(void* const* d_in, const int* in_sizes, int n_in,
                              void* d_out, int out_size) {
    const int*   edge = (const int*)d_in[0];    // [2, E] int32
    const float* emb  = (const float*)d_in[1];  // [N, 128] float32
    float*       out  = (float*)d_out;          // [N, 128] float32

    const int E = in_sizes[0] / 2;
    const int* row = edge;
    const int* col = edge + E;

    k_zero_deg<<<(N_NODES + 255) / 256, 256>>>();
    k_count<<<(E + 255) / 256, 256>>>(row, E);
    k_dinv<<<(N_NODES + 255) / 256, 256>>>();

    // one warp per node: N*32 threads
    {
        long long threads = (long long)N_NODES * 32;
        int blocks = (int)((threads + 255) / 256);
        k_self<<<blocks, 256>>>(emb, out);
    }
    // one warp per edge: E*32 threads
    {
        long long threads = (long long)E * 32;
        int blocks = (int)((threads + 255) / 256);
        k_edge<<<blocks, 256>>>(row, col, emb, out, E);
    }
}

// round 2
// speedup vs baseline: 2.0536x; 2.0536x over previous
#include <cuda_runtime.h>
#include <cstdint>

#define N_NODES 100000
#define EMB_DIM 128
#define MAX_E   1600000

// Scratch (__device__ globals: allocations are forbidden)
__device__ int   g_rdeg[N_NODES];    // source (row) degree -> dinv
__device__ int   g_cdeg[N_NODES];    // destination (col) degree -> bucket sizes
__device__ float g_dinv[N_NODES];
__device__ int   g_off[N_NODES];     // bucket start
__device__ int   g_cursor[N_NODES];  // bucket fill cursor
__device__ int   g_srow[MAX_E];      // grouped-by-col source indices
__device__ int   g_total;

// 1) zero counters
__global__ void k_zero() {
    int i = blockIdx.x * blockDim.x + threadIdx.x;
    if (i < N_NODES) { g_rdeg[i] = 0; g_cdeg[i] = 0; }
    if (i == 0) g_total = 0;
}

// 2) dual histogram over edges
__global__ void k_hist(const int* __restrict__ row, const int* __restrict__ col, int E) {
    int i = blockIdx.x * blockDim.x + threadIdx.x;
    if (i < E) {
        atomicAdd(&g_rdeg[row[i]], 1);
        atomicAdd(&g_cdeg[col[i]], 1);
    }
}

// 3) dinv = rsqrt(rdeg + 1)  (self loop adds 1), and bucket allocation
__global__ void k_dinv_alloc() {
    int i = blockIdx.x * blockDim.x + threadIdx.x;
    if (i < N_NODES) {
        g_dinv[i] = rsqrtf((float)(g_rdeg[i] + 1));
        int o = atomicAdd(&g_total, g_cdeg[i]);
        g_off[i] = o;
        g_cursor[i] = o;
    }
}

// 4) group edges by destination: bucket[col] <- row
__global__ void k_scatter(const int* __restrict__ row, const int* __restrict__ col, int E) {
    int i = blockIdx.x * blockDim.x + threadIdx.x;
    if (i < E) {
        int c = col[i];
        int pos = atomicAdd(&g_cursor[c], 1);
        g_srow[pos] = row[i];
    }
}

// 5) gather + accumulate: one warp per destination node, lane = one float4 chunk.
__global__ void __launch_bounds__(256) k_gather(const float* __restrict__ emb,
                                                float* __restrict__ out) {
    int gtid = blockIdx.x * blockDim.x + threadIdx.x;
    int c    = gtid >> 5;
    int lane = gtid & 31;
    if (c >= N_NODES) return;

    float dc  = g_dinv[c];
    int   beg = g_off[c];
    int   cnt = g_cdeg[c];

    const float4* emb4 = reinterpret_cast<const float4*>(emb);

    // self loop: w = dinv[c]^2
    float4 v = __ldg(&emb4[(size_t)c * 32 + lane]);
    float  ws = dc * dc;
    float4 acc = make_float4(v.x * ws, v.y * ws, v.z * ws, v.w * ws);

    for (int base = 0; base < cnt; base += 32) {
        int jn = min(32, cnt - base);
        // parallel prefetch of indices + weights across lanes
        int   r = 0;
        float w = 0.0f;
        if (lane < jn) {
            r = __ldg(&g_srow[beg + base + lane]);
            w = dc * g_dinv[r];
        }
        #pragma unroll 4
        for (int j = 0; j < jn; j++) {
            int   rj = __shfl_sync(0xffffffffu, r, j);
            float wj = __shfl_sync(0xffffffffu, w, j);
            float4 e = __ldg(&emb4[(size_t)rj * 32 + lane]);
            acc.x = fmaf(wj, e.x, acc.x);
            acc.y = fmaf(wj, e.y, acc.y);
            acc.z = fmaf(wj, e.z, acc.z);
            acc.w = fmaf(wj, e.w, acc.w);
        }
    }
    reinterpret_cast<float4*>(out)[(size_t)c * 32 + lane] = acc;
}

// ---------------------------------------------------------------------------
extern "C" void kernel_launch(void* const* d_in, const int* in_sizes, int n_in,
                              void* d_out, int out_size) {
    const int*   edge = (const int*)d_in[0];    // [2, E] int32
    const float* emb  = (const float*)d_in[1];  // [N, 128] float32
    float*       out  = (float*)d_out;          // [N, 128] float32

    const int E = in_sizes[0] / 2;
    const int* row = edge;
    const int* col = edge + E;

    const int TB = 256;
    k_zero<<<(N_NODES + TB - 1) / TB, TB>>>();
    k_hist<<<(E + TB - 1) / TB, TB>>>(row, col, E);
    k_dinv_alloc<<<(N_NODES + TB - 1) / TB, TB>>>();
    k_scatter<<<(E + TB - 1) / TB, TB>>>(row, col, E);

    long long threads = (long long)N_NODES * 32;
    k_gather<<<(int)((threads + TB - 1) / TB), TB>>>(emb, out);
}